// round 13
// baseline (speedup 1.0000x reference)
#include <cuda_runtime.h>
#include <cstdint>
#include <cstddef>

#define NN   100000
#define EE   1000000
#define ETT  200000
#define FFI  64
#define DDI  32
#define HH   66
#define HS   68          // padded row stride (16B aligned); pad cols always zero
#define LLY  2
#define BN_EPS 1e-5f
#define GMAX 444         // persistent grid cap; surplus blocks exit instantly

static inline int cdiv(int a, int b) { return (a + b - 1) / b; }
static inline int gmin(int a, int b) { return a < b ? a : b; }

// ---------------- scratch (static device globals; zero-initialized) ----------------
__device__ float g_h   [(size_t)NN  * HS];
__device__ float g_ea  [(size_t)EE  * HS];
__device__ float g_tea [(size_t)ETT * HS];
__device__ float g_aggr[(size_t)NN  * HS];   // also: Pb / Rb node tables
__device__ float g_t   [(size_t)NN  * HS];   // also: Pa / Ra node tables
__device__ float g_z   [(size_t)NN  * HS];
__device__ float g_ehid[(size_t)ETT * HS];   // Ptea edge table (stride 68)
__device__ float g_o1  [(size_t)ETT * 52];   // Rtea edge table (stride 52)
__device__ float g_sum[HH];
__device__ float g_sumsq[HH];
__device__ float g_mean[HH];
__device__ float g_invstd[HH];
__device__ float g_zerob[HS];                // never written: zero bias
// CSR scratch
__device__ int g_cnt[NN];
__device__ int g_rowstart[NN + 1];
__device__ int g_cursor[NN];
__device__ int g_bsum[128];
__device__ int g_boff[128];
__device__ int g_perm[EE];
__device__ int g_srcs[EE];
// persistent-GEMM work counters
__device__ int g_work[32];

// ================= CSR build =================
__global__ void zero_cnt_kernel()
{
    int i = blockIdx.x * blockDim.x + threadIdx.x;
    if (i < NN) g_cnt[i] = 0;
    if (blockIdx.x == 0 && threadIdx.x < 32) g_work[threadIdx.x] = 0;
}

__global__ void hist_kernel(const int* __restrict__ dst)
{
    int e = blockIdx.x * blockDim.x + threadIdx.x;
    if (e < EE) atomicAdd(&g_cnt[dst[e]], 1);
}

__global__ void scan1_kernel()
{
    __shared__ int sh[1024];
    int i = blockIdx.x * 1024 + threadIdx.x;
    int v = (i < NN) ? g_cnt[i] : 0;
    sh[threadIdx.x] = v;
    __syncthreads();
    for (int off = 1; off < 1024; off <<= 1) {
        int t = (threadIdx.x >= off) ? sh[threadIdx.x - off] : 0;
        __syncthreads();
        sh[threadIdx.x] += t;
        __syncthreads();
    }
    if (i < NN) g_rowstart[i] = sh[threadIdx.x] - v;
    if (threadIdx.x == 1023) g_bsum[blockIdx.x] = sh[1023];
}

__global__ void scan2_kernel(int nb)
{
    __shared__ int sh[128];
    int t = threadIdx.x;
    int v = (t < nb) ? g_bsum[t] : 0;
    sh[t] = v;
    __syncthreads();
    for (int off = 1; off < 128; off <<= 1) {
        int u = (t >= off) ? sh[t - off] : 0;
        __syncthreads();
        sh[t] += u;
        __syncthreads();
    }
    g_boff[t] = sh[t] - v;
}

__global__ void scan3_kernel()
{
    int i = blockIdx.x * blockDim.x + threadIdx.x;
    if (i < NN) {
        int rs = g_rowstart[i] + g_boff[i >> 10];
        g_rowstart[i] = rs;
        g_cursor[i] = rs;
    }
    if (i == 0) g_rowstart[NN] = EE;
}

__global__ void place_kernel(const int* __restrict__ src, const int* __restrict__ dst)
{
    int e = blockIdx.x * blockDim.x + threadIdx.x;
    if (e >= EE) return;
    int d = dst[e];
    int pos = atomicAdd(&g_cursor[d], 1);
    g_perm[pos] = e;
    g_srcs[pos] = src[e];
}

// ================= persistent 2-row blocked tall-skinny GEMM =================
// MODE 0: plain; 1: relu; 2: out += 0.5*(A@W+b). RELUIN: relu(A rows).
// COMB: A row r := relu(Pa[ts[r]] + Pb[td[r]] + A[r])  (all stride KP)
template <int K, int HOUT, int MODE, bool GATHER, bool RELUIN, bool COMB>
__global__ void __launch_bounds__(128)
rowgemm2(const float* __restrict__ A, const float* __restrict__ W,
         const float* __restrict__ bias, float* __restrict__ out,
         const int* __restrict__ perm, int M, int slot,
         const float* __restrict__ Pa, const float* __restrict__ Pb,
         const int* __restrict__ ts, const int* __restrict__ td)
{
    constexpr int KP = (K + 3) & ~3;
    constexpr int HP = (HOUT + 3) & ~3;
    __shared__ float sW[KP * HP];
    __shared__ float sb[HP];
    __shared__ int s_base;
    for (int i = threadIdx.x; i < KP * HP; i += 128) {
        int k = i / HP, j = i % HP;
        sW[i] = (k < K && j < HOUT) ? W[k * HOUT + j] : 0.0f;
    }
    for (int i = threadIdx.x; i < HP; i += 128)
        sb[i] = (i < HOUT) ? bias[i] : 0.0f;

    for (;;) {
        __syncthreads();
        if (threadIdx.x == 0) s_base = atomicAdd(&g_work[slot], 1);
        __syncthreads();
        int base = s_base * 256;
        if (base >= M) return;
        int r0 = base + threadIdx.x;
        if (r0 < M) {
            int r1 = r0 + 128;
            bool v1 = (r1 < M);
            int ra0 = GATHER ? perm[r0] : r0;
            int ra1 = v1 ? (GATHER ? perm[r1] : r1) : ra0;
            int rb1 = v1 ? r1 : r0;

            float acc0[HP], acc1[HP];
#pragma unroll
            for (int j = 0; j < HP; j++) { acc0[j] = sb[j]; acc1[j] = sb[j]; }

            const float4* a40 = reinterpret_cast<const float4*>(A + (size_t)ra0 * KP);
            const float4* a41 = reinterpret_cast<const float4*>(A + (size_t)ra1 * KP);
            const float4 *pa0 = nullptr, *pb0 = nullptr, *pa1 = nullptr, *pb1 = nullptr;
            if (COMB) {
                pa0 = reinterpret_cast<const float4*>(Pa + (size_t)ts[r0] * KP);
                pb0 = reinterpret_cast<const float4*>(Pb + (size_t)td[r0] * KP);
                pa1 = reinterpret_cast<const float4*>(Pa + (size_t)ts[rb1] * KP);
                pb1 = reinterpret_cast<const float4*>(Pb + (size_t)td[rb1] * KP);
            }
#pragma unroll 1
            for (int kk = 0; kk < KP / 4; kk++) {
                float4 av0 = __ldg(&a40[kk]);
                float4 av1 = __ldg(&a41[kk]);
                if (COMB) {
                    float4 x0 = __ldg(&pa0[kk]), y0 = __ldg(&pb0[kk]);
                    float4 x1 = __ldg(&pa1[kk]), y1 = __ldg(&pb1[kk]);
                    av0.x = fmaxf(av0.x + x0.x + y0.x, 0.f);
                    av0.y = fmaxf(av0.y + x0.y + y0.y, 0.f);
                    av0.z = fmaxf(av0.z + x0.z + y0.z, 0.f);
                    av0.w = fmaxf(av0.w + x0.w + y0.w, 0.f);
                    av1.x = fmaxf(av1.x + x1.x + y1.x, 0.f);
                    av1.y = fmaxf(av1.y + x1.y + y1.y, 0.f);
                    av1.z = fmaxf(av1.z + x1.z + y1.z, 0.f);
                    av1.w = fmaxf(av1.w + x1.w + y1.w, 0.f);
                }
                if (RELUIN) {
                    av0.x = fmaxf(av0.x, 0.f); av0.y = fmaxf(av0.y, 0.f);
                    av0.z = fmaxf(av0.z, 0.f); av0.w = fmaxf(av0.w, 0.f);
                    av1.x = fmaxf(av1.x, 0.f); av1.y = fmaxf(av1.y, 0.f);
                    av1.z = fmaxf(av1.z, 0.f); av1.w = fmaxf(av1.w, 0.f);
                }
#pragma unroll
                for (int s = 0; s < 4; s++) {
                    float a0 = (s == 0) ? av0.x : (s == 1) ? av0.y : (s == 2) ? av0.z : av0.w;
                    float a1 = (s == 0) ? av1.x : (s == 1) ? av1.y : (s == 2) ? av1.z : av1.w;
                    const float4* w4 = reinterpret_cast<const float4*>(&sW[(kk * 4 + s) * HP]);
#pragma unroll
                    for (int j = 0; j < HP / 4; j++) {
                        float4 w = w4[j];
                        acc0[4 * j + 0] = fmaf(a0, w.x, acc0[4 * j + 0]);
                        acc0[4 * j + 1] = fmaf(a0, w.y, acc0[4 * j + 1]);
                        acc0[4 * j + 2] = fmaf(a0, w.z, acc0[4 * j + 2]);
                        acc0[4 * j + 3] = fmaf(a0, w.w, acc0[4 * j + 3]);
                        acc1[4 * j + 0] = fmaf(a1, w.x, acc1[4 * j + 0]);
                        acc1[4 * j + 1] = fmaf(a1, w.y, acc1[4 * j + 1]);
                        acc1[4 * j + 2] = fmaf(a1, w.z, acc1[4 * j + 2]);
                        acc1[4 * j + 3] = fmaf(a1, w.w, acc1[4 * j + 3]);
                    }
                }
            }

            float4* o40 = reinterpret_cast<float4*>(out + (size_t)r0 * HP);
#pragma unroll
            for (int j = 0; j < HP / 4; j++) {
                float4 v;
                v.x = acc0[4 * j + 0]; v.y = acc0[4 * j + 1];
                v.z = acc0[4 * j + 2]; v.w = acc0[4 * j + 3];
                if (MODE == 1) {
                    v.x = fmaxf(v.x, 0.f); v.y = fmaxf(v.y, 0.f);
                    v.z = fmaxf(v.z, 0.f); v.w = fmaxf(v.w, 0.f);
                }
                if (MODE == 2) {
                    float4 ov = o40[j];
                    v.x = ov.x + 0.5f * v.x; v.y = ov.y + 0.5f * v.y;
                    v.z = ov.z + 0.5f * v.z; v.w = ov.w + 0.5f * v.w;
                }
                o40[j] = v;
            }
            if (v1) {
                float4* o41 = reinterpret_cast<float4*>(out + (size_t)r1 * HP);
#pragma unroll
                for (int j = 0; j < HP / 4; j++) {
                    float4 v;
                    v.x = acc1[4 * j + 0]; v.y = acc1[4 * j + 1];
                    v.z = acc1[4 * j + 2]; v.w = acc1[4 * j + 3];
                    if (MODE == 1) {
                        v.x = fmaxf(v.x, 0.f); v.y = fmaxf(v.y, 0.f);
                        v.z = fmaxf(v.z, 0.f); v.w = fmaxf(v.w, 0.f);
                    }
                    if (MODE == 2) {
                        float4 ov = o41[j];
                        v.x = ov.x + 0.5f * v.x; v.y = ov.y + 0.5f * v.y;
                        v.z = ov.z + 0.5f * v.z; v.w = ov.w + 0.5f * v.w;
                    }
                    o41[j] = v;
                }
            }
        }
    }
}

// ================= aggregation (float2 lanes, 2-edge unroll) =================
__global__ void aggregate_kernel(const float* __restrict__ h, const float* __restrict__ ea,
                                 float* __restrict__ aggr)
{
    int warp = (blockIdx.x * blockDim.x + threadIdx.x) >> 5;
    int lane = threadIdx.x & 31;
    if (warp >= NN) return;
    int beg = g_rowstart[warp];
    int end = g_rowstart[warp + 1];
    bool has2 = lane < 2;
    int c2 = 32 + lane;                 // float2 index 32,33 (floats 64..67)
    float2 a0 = make_float2(0.f, 0.f);  // even-p partial
    float2 a1 = make_float2(0.f, 0.f);
    float2 b0 = make_float2(0.f, 0.f);  // odd-p partial
    float2 b1 = make_float2(0.f, 0.f);
    int p = beg;
    for (; p + 1 < end; p += 2) {
        int s0 = g_srcs[p];
        int s1 = g_srcs[p + 1];
        const float2* er0 = reinterpret_cast<const float2*>(ea + (size_t)p * HS);
        const float2* er1 = reinterpret_cast<const float2*>(ea + (size_t)(p + 1) * HS);
        const float2* hr0 = reinterpret_cast<const float2*>(h + (size_t)s0 * HS);
        const float2* hr1 = reinterpret_cast<const float2*>(h + (size_t)s1 * HS);
        float2 e0 = er0[lane], h0 = hr0[lane];
        float2 e1 = er1[lane], h1 = hr1[lane];
        a0.x += fmaxf(h0.x + e0.x, 0.f);
        a0.y += fmaxf(h0.y + e0.y, 0.f);
        b0.x += fmaxf(h1.x + e1.x, 0.f);
        b0.y += fmaxf(h1.y + e1.y, 0.f);
        if (has2) {
            float2 e0t = er0[c2], h0t = hr0[c2];
            float2 e1t = er1[c2], h1t = hr1[c2];
            a1.x += fmaxf(h0t.x + e0t.x, 0.f);
            a1.y += fmaxf(h0t.y + e0t.y, 0.f);
            b1.x += fmaxf(h1t.x + e1t.x, 0.f);
            b1.y += fmaxf(h1t.y + e1t.y, 0.f);
        }
    }
    if (p < end) {
        int s0 = g_srcs[p];
        const float2* er0 = reinterpret_cast<const float2*>(ea + (size_t)p * HS);
        const float2* hr0 = reinterpret_cast<const float2*>(h + (size_t)s0 * HS);
        float2 e0 = er0[lane], h0 = hr0[lane];
        a0.x += fmaxf(h0.x + e0.x, 0.f);
        a0.y += fmaxf(h0.y + e0.y, 0.f);
        if (has2) {
            float2 e0t = er0[c2], h0t = hr0[c2];
            a1.x += fmaxf(h0t.x + e0t.x, 0.f);
            a1.y += fmaxf(h0t.y + e0t.y, 0.f);
        }
    }
    const float2* hd = reinterpret_cast<const float2*>(h + (size_t)warp * HS);
    float2* o = reinterpret_cast<float2*>(aggr + (size_t)warp * HS);
    float2 hv = hd[lane];
    float2 ov;
    ov.x = hv.x + a0.x + b0.x;
    ov.y = hv.y + a0.y + b0.y;
    o[lane] = ov;
    if (has2) {
        float2 hv2 = hd[c2];
        float2 ov2;
        ov2.x = hv2.x + a1.x + b1.x;
        ov2.y = hv2.y + a1.y + b1.y;
        o[c2] = ov2;
    }
}

// ================= BN =================
__global__ void bnstats_kernel(const float* __restrict__ z, int M)
{
    __shared__ float ssum[8][HH + 2];
    __shared__ float ssq [8][HH + 2];
    int c  = threadIdx.x;
    int ty = threadIdx.y;
    float s = 0.f, q = 0.f;
    for (int r = blockIdx.x * 8 + ty; r < M; r += gridDim.x * 8) {
        float v = z[(size_t)r * HS + c];
        s += v; q += v * v;
    }
    ssum[ty][c] = s; ssq[ty][c] = q;
    __syncthreads();
    for (int off = 4; off >= 1; off >>= 1) {
        if (ty < off) { ssum[ty][c] += ssum[ty + off][c]; ssq[ty][c] += ssq[ty + off][c]; }
        __syncthreads();
    }
    if (ty == 0) {
        atomicAdd(&g_sum[c],   ssum[0][c]);
        atomicAdd(&g_sumsq[c], ssq[0][c]);
    }
}

__global__ void bnfinal_kernel(int n)
{
    int c = threadIdx.x;
    if (c < HH) {
        float m = g_sum[c] / (float)n;
        float v = g_sumsq[c] / (float)n - m * m;
        g_mean[c] = m;
        g_invstd[c] = rsqrtf(v + BN_EPS);
        g_sum[c] = 0.0f;
        g_sumsq[c] = 0.0f;
    }
}

__global__ void hup_kernel(const float* __restrict__ gamma, const float* __restrict__ beta, int M)
{
    int c = threadIdx.x;
    int r = blockIdx.x * blockDim.y + threadIdx.y;
    if (r >= M) return;
    size_t i = (size_t)r * HS + c;
    float bn = (g_z[i] - g_mean[c]) * g_invstd[c] * gamma[c] + beta[c];
    g_h[i] = 0.5f * (g_h[i] + fmaxf(bn, 0.0f));
}

// ================= persistent final MLP layers 2+3 (COMB input) =================
__global__ void __launch_bounds__(128)
f23_kernel(const float* __restrict__ Rt, const float* __restrict__ Ra,
           const float* __restrict__ Rb,
           const int* __restrict__ ts, const int* __restrict__ td,
           const float* __restrict__ W2, const float* __restrict__ b2,
           const float* __restrict__ W3, const float* __restrict__ b3,
           float* __restrict__ out, int M, int slot)
{
    __shared__ float sW2[52 * 28];
    __shared__ float sW3[25 * 4];
    __shared__ float sb2[28];
    __shared__ float sb3[2];
    __shared__ int s_base;
    for (int i = threadIdx.x; i < 52 * 28; i += 128) {
        int k = i / 28, j = i % 28;
        sW2[i] = (k < 50 && j < 25) ? W2[k * 25 + j] : 0.0f;
    }
    for (int i = threadIdx.x; i < 25 * 4; i += 128) {
        int k = i / 4, j = i % 4;
        sW3[i] = (j < 2) ? W3[k * 2 + j] : 0.0f;
    }
    if (threadIdx.x < 28) sb2[threadIdx.x] = (threadIdx.x < 25) ? b2[threadIdx.x] : 0.0f;
    if (threadIdx.x < 2)  sb3[threadIdx.x] = b3[threadIdx.x];

    for (;;) {
        __syncthreads();
        if (threadIdx.x == 0) s_base = atomicAdd(&g_work[slot], 1);
        __syncthreads();
        int base = s_base * 256;
        if (base >= M) return;
        int r0 = base + threadIdx.x;
        if (r0 < M) {
            int r1 = r0 + 128;
            bool v1 = (r1 < M);
            int rb = v1 ? r1 : r0;

            float acc0[28], acc1[28];
#pragma unroll
            for (int j = 0; j < 28; j++) { acc0[j] = sb2[j]; acc1[j] = sb2[j]; }

            const float4* t40 = reinterpret_cast<const float4*>(Rt + (size_t)r0 * 52);
            const float4* t41 = reinterpret_cast<const float4*>(Rt + (size_t)rb * 52);
            const float4* pa0 = reinterpret_cast<const float4*>(Ra + (size_t)ts[r0] * 52);
            const float4* pb0 = reinterpret_cast<const float4*>(Rb + (size_t)td[r0] * 52);
            const float4* pa1 = reinterpret_cast<const float4*>(Ra + (size_t)ts[rb] * 52);
            const float4* pb1 = reinterpret_cast<const float4*>(Rb + (size_t)td[rb] * 52);
#pragma unroll 1
            for (int kk = 0; kk < 13; kk++) {
                float4 av0 = __ldg(&t40[kk]);
                float4 av1 = __ldg(&t41[kk]);
                float4 x0 = __ldg(&pa0[kk]), y0 = __ldg(&pb0[kk]);
                float4 x1 = __ldg(&pa1[kk]), y1 = __ldg(&pb1[kk]);
                av0.x = fmaxf(av0.x + x0.x + y0.x, 0.f);
                av0.y = fmaxf(av0.y + x0.y + y0.y, 0.f);
                av0.z = fmaxf(av0.z + x0.z + y0.z, 0.f);
                av0.w = fmaxf(av0.w + x0.w + y0.w, 0.f);
                av1.x = fmaxf(av1.x + x1.x + y1.x, 0.f);
                av1.y = fmaxf(av1.y + x1.y + y1.y, 0.f);
                av1.z = fmaxf(av1.z + x1.z + y1.z, 0.f);
                av1.w = fmaxf(av1.w + x1.w + y1.w, 0.f);
#pragma unroll
                for (int s = 0; s < 4; s++) {
                    float a0 = (s == 0) ? av0.x : (s == 1) ? av0.y : (s == 2) ? av0.z : av0.w;
                    float a1 = (s == 0) ? av1.x : (s == 1) ? av1.y : (s == 2) ? av1.z : av1.w;
                    const float4* w4 = reinterpret_cast<const float4*>(&sW2[(kk * 4 + s) * 28]);
#pragma unroll
                    for (int j = 0; j < 7; j++) {
                        float4 w = w4[j];
                        acc0[4 * j + 0] = fmaf(a0, w.x, acc0[4 * j + 0]);
                        acc0[4 * j + 1] = fmaf(a0, w.y, acc0[4 * j + 1]);
                        acc0[4 * j + 2] = fmaf(a0, w.z, acc0[4 * j + 2]);
                        acc0[4 * j + 3] = fmaf(a0, w.w, acc0[4 * j + 3]);
                        acc1[4 * j + 0] = fmaf(a1, w.x, acc1[4 * j + 0]);
                        acc1[4 * j + 1] = fmaf(a1, w.y, acc1[4 * j + 1]);
                        acc1[4 * j + 2] = fmaf(a1, w.z, acc1[4 * j + 2]);
                        acc1[4 * j + 3] = fmaf(a1, w.w, acc1[4 * j + 3]);
                    }
                }
            }

            float o00 = sb3[0], o01 = sb3[1], o10 = sb3[0], o11 = sb3[1];
#pragma unroll
            for (int k = 0; k < 25; k++) {
                float w0 = sW3[k * 4 + 0], w1 = sW3[k * 4 + 1];
                float a0 = fmaxf(acc0[k], 0.f);
                float a1 = fmaxf(acc1[k], 0.f);
                o00 = fmaf(a0, w0, o00); o01 = fmaf(a0, w1, o01);
                o10 = fmaf(a1, w0, o10); o11 = fmaf(a1, w1, o11);
            }
            out[(size_t)r0 * 2 + 0] = o00;
            out[(size_t)r0 * 2 + 1] = o01;
            if (v1) {
                out[(size_t)r1 * 2 + 0] = o10;
                out[(size_t)r1 * 2 + 1] = o11;
            }
        }
    }
}

// =======================================================================================
extern "C" void kernel_launch(void* const* d_in, const int* in_sizes, int n_in,
                              void* d_out, int out_size)
{
    const float *x, *edge_attr, *tea_in, *node_w, *node_b, *edge_w, *edge_b;
    const float *conv_w1, *conv_b1, *conv_w2, *conv_b2, *bn_gamma, *bn_beta;
    const float *emlp_w1, *emlp_b1, *emlp_w2, *emlp_b2;
    const float *mlp_w1, *mlp_b1, *mlp_w2, *mlp_b2, *mlp_w3, *mlp_b3;
    const int *edge_index, *eli;

    if (in_sizes[1] == 2 * EE) {
        x          = (const float*)d_in[0];
        edge_index = (const int*)  d_in[1];
        edge_attr  = (const float*)d_in[2];
        eli        = (const int*)  d_in[3];
        tea_in     = (const float*)d_in[4];
        node_w = (const float*)d_in[5];  node_b = (const float*)d_in[6];
        edge_w = (const float*)d_in[7];  edge_b = (const float*)d_in[8];
        conv_w1 = (const float*)d_in[9];  conv_b1 = (const float*)d_in[10];
        conv_w2 = (const float*)d_in[11]; conv_b2 = (const float*)d_in[12];
        bn_gamma = (const float*)d_in[13]; bn_beta = (const float*)d_in[14];
        emlp_w1 = (const float*)d_in[15]; emlp_b1 = (const float*)d_in[16];
        emlp_w2 = (const float*)d_in[17]; emlp_b2 = (const float*)d_in[18];
        mlp_w1 = (const float*)d_in[19]; mlp_b1 = (const float*)d_in[20];
        mlp_w2 = (const float*)d_in[21]; mlp_b2 = (const float*)d_in[22];
        mlp_w3 = (const float*)d_in[23]; mlp_b3 = (const float*)d_in[24];
    } else {
        x         = (const float*)d_in[0];
        edge_attr = (const float*)d_in[1];
        tea_in    = (const float*)d_in[2];
        node_w = (const float*)d_in[3];  node_b = (const float*)d_in[4];
        edge_w = (const float*)d_in[5];  edge_b = (const float*)d_in[6];
        conv_w1 = (const float*)d_in[7];  conv_b1 = (const float*)d_in[8];
        conv_w2 = (const float*)d_in[9];  conv_b2 = (const float*)d_in[10];
        bn_gamma = (const float*)d_in[11]; bn_beta = (const float*)d_in[12];
        emlp_w1 = (const float*)d_in[13]; emlp_b1 = (const float*)d_in[14];
        emlp_w2 = (const float*)d_in[15]; emlp_b2 = (const float*)d_in[16];
        mlp_w1 = (const float*)d_in[17]; mlp_b1 = (const float*)d_in[18];
        mlp_w2 = (const float*)d_in[19]; mlp_b2 = (const float*)d_in[20];
        mlp_w3 = (const float*)d_in[21]; mlp_b3 = (const float*)d_in[22];
        edge_index = (const int*)d_in[23];
        eli        = (const int*)d_in[24];
    }

    const int* e_src = edge_index;
    const int* e_dst = edge_index + EE;
    const int* tsrc  = eli;
    const int* tdst  = eli + ETT;

    float *p_h, *p_ea, *p_tea, *p_aggr, *p_t, *p_z, *p_ehid, *p_o1, *p_zb;
    int *p_perm;
    cudaGetSymbolAddress((void**)&p_h,    g_h);
    cudaGetSymbolAddress((void**)&p_ea,   g_ea);
    cudaGetSymbolAddress((void**)&p_tea,  g_tea);
    cudaGetSymbolAddress((void**)&p_aggr, g_aggr);
    cudaGetSymbolAddress((void**)&p_t,    g_t);
    cudaGetSymbolAddress((void**)&p_z,    g_z);
    cudaGetSymbolAddress((void**)&p_ehid, g_ehid);
    cudaGetSymbolAddress((void**)&p_o1,   g_o1);
    cudaGetSymbolAddress((void**)&p_zb,   g_zerob);
    cudaGetSymbolAddress((void**)&p_perm, g_perm);

    // ---- CSR build (also zeroes g_work) ----
    zero_cnt_kernel<<<cdiv(NN, 256), 256>>>();
    hist_kernel<<<cdiv(EE, 256), 256>>>(e_dst);
    scan1_kernel<<<cdiv(NN, 1024), 1024>>>();
    scan2_kernel<<<1, 128>>>(cdiv(NN, 1024));
    scan3_kernel<<<cdiv(NN, 256), 256>>>();
    place_kernel<<<cdiv(EE, 256), 256>>>(e_src, e_dst);

    // ---- embeddings (persistent, slots 0-2) ----
    rowgemm2<FFI, HH, 0, false, false, false><<<gmin(cdiv(NN, 256), GMAX), 128>>>(
        x, node_w, node_b, p_h, nullptr, NN, 0, nullptr, nullptr, nullptr, nullptr);
    rowgemm2<DDI, HH, 0, true, false, false><<<gmin(cdiv(EE, 256), GMAX), 128>>>(
        edge_attr, edge_w, edge_b, p_ea, p_perm, EE, 1, nullptr, nullptr, nullptr, nullptr);
    rowgemm2<DDI, HH, 0, false, false, false><<<gmin(cdiv(ETT, 256), GMAX), 128>>>(
        tea_in, edge_w, edge_b, p_tea, nullptr, ETT, 2, nullptr, nullptr, nullptr, nullptr);

    // ---- layers ----
    for (int l = 0; l < LLY; l++) {
        int s0 = 3 + l * 6;
        const float* W1 = emlp_w1 + l * 3 * HH * HH;   // rows 0-65=a, 66-131=b, 132-197=c
        aggregate_kernel<<<cdiv(NN, 8), 256>>>(p_h, p_ea, p_aggr);
        rowgemm2<HH, HH, 1, false, false, false><<<gmin(cdiv(NN, 256), GMAX), 128>>>(
            p_aggr, conv_w1 + l * HH * HH, conv_b1 + l * HH, p_t, nullptr, NN, s0,
            nullptr, nullptr, nullptr, nullptr);
        rowgemm2<HH, HH, 0, false, false, false><<<gmin(cdiv(NN, 256), GMAX), 128>>>(
            p_t, conv_w2 + l * HH * HH, conv_b2 + l * HH, p_z, nullptr, NN, s0 + 1,
            nullptr, nullptr, nullptr, nullptr);
        {
            dim3 bs(HH, 8);
            bnstats_kernel<<<264, bs>>>(p_z, NN);
        }
        bnfinal_kernel<<<1, HH>>>(NN);
        {
            dim3 bs(HH, 4);
            hup_kernel<<<cdiv(NN, 4), bs>>>(bn_gamma + l * HH, bn_beta + l * HH, NN);
        }
        // edge update, factored + fused combine:
        rowgemm2<HH, HH, 0, false, false, false><<<gmin(cdiv(NN, 256), GMAX), 128>>>(
            p_h, W1, p_zb, p_t, nullptr, NN, s0 + 2, nullptr, nullptr, nullptr, nullptr);
        rowgemm2<HH, HH, 0, false, false, false><<<gmin(cdiv(NN, 256), GMAX), 128>>>(
            p_h, W1 + HH * HH, p_zb, p_aggr, nullptr, NN, s0 + 3, nullptr, nullptr, nullptr, nullptr);
        rowgemm2<HH, HH, 0, false, false, false><<<gmin(cdiv(ETT, 256), GMAX), 128>>>(
            p_tea, W1 + 2 * HH * HH, emlp_b1 + l * HH, p_ehid, nullptr, ETT, s0 + 4,
            nullptr, nullptr, nullptr, nullptr);
        // tea += 0.5*(relu(Pa[ts]+Pb[td]+Ptea) @ W2 + b2)
        rowgemm2<HH, HH, 2, false, false, true><<<gmin(cdiv(ETT, 256), GMAX), 128>>>(
            p_ehid, emlp_w2 + l * HH * HH, emlp_b2 + l * HH, p_tea, nullptr, ETT, s0 + 5,
            p_t, p_aggr, tsrc, tdst);
    }

    // ---- final classifier, factored + fused combine (slots 15-18) ----
    rowgemm2<HH, 50, 0, false, true, false><<<gmin(cdiv(NN, 256), GMAX), 128>>>(
        p_h, mlp_w1, p_zb, p_t, nullptr, NN, 15, nullptr, nullptr, nullptr, nullptr);
    rowgemm2<HH, 50, 0, false, true, false><<<gmin(cdiv(NN, 256), GMAX), 128>>>(
        p_h, mlp_w1 + HH * 50, p_zb, p_aggr, nullptr, NN, 16, nullptr, nullptr, nullptr, nullptr);
    rowgemm2<HH, 50, 0, false, false, false><<<gmin(cdiv(ETT, 256), GMAX), 128>>>(
        p_tea, mlp_w1 + 2 * HH * 50, mlp_b1, p_o1, nullptr, ETT, 17,
        nullptr, nullptr, nullptr, nullptr);
    f23_kernel<<<gmin(cdiv(ETT, 256), GMAX), 128>>>(p_o1, p_t, p_aggr, tsrc, tdst,
                                                    mlp_w2, mlp_b2, mlp_w3, mlp_b3,
                                                    (float*)d_out, ETT, 18);
}

// round 14
// speedup vs baseline: 1.0765x; 1.0765x over previous
#include <cuda_runtime.h>
#include <cstdint>
#include <cstddef>

#define NN   100000
#define EE   1000000
#define ETT  200000
#define FFI  64
#define DDI  32
#define HH   66
#define HS   68          // padded row stride (16B aligned); pad cols always zero
#define LLY  2
#define BN_EPS 1e-5f
#define GMAX 444         // persistent grid cap; surplus blocks exit instantly

static inline int cdiv(int a, int b) { return (a + b - 1) / b; }
static inline int gmin(int a, int b) { return a < b ? a : b; }

// ---------------- scratch (static device globals; zero-initialized) ----------------
__device__ float g_h   [(size_t)NN  * HS];
__device__ float g_ea  [(size_t)EE  * HS];
__device__ float g_tea [(size_t)ETT * HS];
__device__ float g_aggr[(size_t)NN  * HS];   // also: Pb / Rb node tables
__device__ float g_t   [(size_t)NN  * HS];   // also: Pa / Ra node tables
__device__ float g_z   [(size_t)NN  * HS];
__device__ float g_ehid[(size_t)ETT * HS];   // Ptea edge table (stride 68)
__device__ float g_o1  [(size_t)ETT * 52];   // Rtea edge table (stride 52)
__device__ float g_sum[HH];
__device__ float g_sumsq[HH];
__device__ float g_mean[HH];
__device__ float g_invstd[HH];
__device__ float g_zerob[HS];                // never written: zero bias
// CSR scratch
__device__ int g_cnt[NN];
__device__ int g_rowstart[NN + 1];
__device__ int g_cursor[NN];
__device__ int g_bsum[128];
__device__ int g_boff[128];
__device__ int g_perm[EE];
__device__ int g_srcs[EE];
// persistent-GEMM work counters
__device__ int g_work[32];

// ================= CSR build =================
__global__ void zero_cnt_kernel()
{
    int i = blockIdx.x * blockDim.x + threadIdx.x;
    if (i < NN) g_cnt[i] = 0;
    if (blockIdx.x == 0 && threadIdx.x < 32) g_work[threadIdx.x] = 0;
}

__global__ void hist_kernel(const int* __restrict__ dst)
{
    int e = blockIdx.x * blockDim.x + threadIdx.x;
    if (e < EE) atomicAdd(&g_cnt[dst[e]], 1);
}

__global__ void scan1_kernel()
{
    __shared__ int sh[1024];
    int i = blockIdx.x * 1024 + threadIdx.x;
    int v = (i < NN) ? g_cnt[i] : 0;
    sh[threadIdx.x] = v;
    __syncthreads();
    for (int off = 1; off < 1024; off <<= 1) {
        int t = (threadIdx.x >= off) ? sh[threadIdx.x - off] : 0;
        __syncthreads();
        sh[threadIdx.x] += t;
        __syncthreads();
    }
    if (i < NN) g_rowstart[i] = sh[threadIdx.x] - v;
    if (threadIdx.x == 1023) g_bsum[blockIdx.x] = sh[1023];
}

__global__ void scan2_kernel(int nb)
{
    __shared__ int sh[128];
    int t = threadIdx.x;
    int v = (t < nb) ? g_bsum[t] : 0;
    sh[t] = v;
    __syncthreads();
    for (int off = 1; off < 128; off <<= 1) {
        int u = (t >= off) ? sh[t - off] : 0;
        __syncthreads();
        sh[t] += u;
        __syncthreads();
    }
    g_boff[t] = sh[t] - v;
}

__global__ void scan3_kernel()
{
    int i = blockIdx.x * blockDim.x + threadIdx.x;
    if (i < NN) {
        int rs = g_rowstart[i] + g_boff[i >> 10];
        g_rowstart[i] = rs;
        g_cursor[i] = rs;
    }
    if (i == 0) g_rowstart[NN] = EE;
}

__global__ void place_kernel(const int* __restrict__ src, const int* __restrict__ dst)
{
    int e = blockIdx.x * blockDim.x + threadIdx.x;
    if (e >= EE) return;
    int d = dst[e];
    int pos = atomicAdd(&g_cursor[d], 1);
    g_perm[pos] = e;
    g_srcs[pos] = src[e];
}

// ================= persistent 2-row blocked tall-skinny GEMM =================
// MODE 0: plain; 1: relu; 2: out += 0.5*(A@W+b). RELUIN: relu(A rows).
// COMB: A row r := relu(Pa[ts[r]] + Pb[td[r]] + A[r])  (all stride KP)
template <int K, int HOUT, int MODE, bool GATHER, bool RELUIN, bool COMB>
__global__ void __launch_bounds__(128)
rowgemm2(const float* __restrict__ A, const float* __restrict__ W,
         const float* __restrict__ bias, float* __restrict__ out,
         const int* __restrict__ perm, int M, int slot,
         const float* __restrict__ Pa, const float* __restrict__ Pb,
         const int* __restrict__ ts, const int* __restrict__ td)
{
    constexpr int KP = (K + 3) & ~3;
    constexpr int HP = (HOUT + 3) & ~3;
    __shared__ float sW[KP * HP];
    __shared__ float sb[HP];
    __shared__ int s_base;
    for (int i = threadIdx.x; i < KP * HP; i += 128) {
        int k = i / HP, j = i % HP;
        sW[i] = (k < K && j < HOUT) ? W[k * HOUT + j] : 0.0f;
    }
    for (int i = threadIdx.x; i < HP; i += 128)
        sb[i] = (i < HOUT) ? bias[i] : 0.0f;

    for (;;) {
        __syncthreads();
        if (threadIdx.x == 0) s_base = atomicAdd(&g_work[slot], 1);
        __syncthreads();
        int base = s_base * 256;
        if (base >= M) return;
        int r0 = base + threadIdx.x;
        if (r0 < M) {
            int r1 = r0 + 128;
            bool v1 = (r1 < M);
            int ra0 = GATHER ? perm[r0] : r0;
            int ra1 = v1 ? (GATHER ? perm[r1] : r1) : ra0;
            int rb1 = v1 ? r1 : r0;

            float acc0[HP], acc1[HP];
#pragma unroll
            for (int j = 0; j < HP; j++) { acc0[j] = sb[j]; acc1[j] = sb[j]; }

            const float4* a40 = reinterpret_cast<const float4*>(A + (size_t)ra0 * KP);
            const float4* a41 = reinterpret_cast<const float4*>(A + (size_t)ra1 * KP);
            const float4 *pa0 = nullptr, *pb0 = nullptr, *pa1 = nullptr, *pb1 = nullptr;
            if (COMB) {
                pa0 = reinterpret_cast<const float4*>(Pa + (size_t)ts[r0] * KP);
                pb0 = reinterpret_cast<const float4*>(Pb + (size_t)td[r0] * KP);
                pa1 = reinterpret_cast<const float4*>(Pa + (size_t)ts[rb1] * KP);
                pb1 = reinterpret_cast<const float4*>(Pb + (size_t)td[rb1] * KP);
            }
#pragma unroll 1
            for (int kk = 0; kk < KP / 4; kk++) {
                float4 av0 = __ldg(&a40[kk]);
                float4 av1 = __ldg(&a41[kk]);
                if (COMB) {
                    float4 x0 = __ldg(&pa0[kk]), y0 = __ldg(&pb0[kk]);
                    float4 x1 = __ldg(&pa1[kk]), y1 = __ldg(&pb1[kk]);
                    av0.x = fmaxf(av0.x + x0.x + y0.x, 0.f);
                    av0.y = fmaxf(av0.y + x0.y + y0.y, 0.f);
                    av0.z = fmaxf(av0.z + x0.z + y0.z, 0.f);
                    av0.w = fmaxf(av0.w + x0.w + y0.w, 0.f);
                    av1.x = fmaxf(av1.x + x1.x + y1.x, 0.f);
                    av1.y = fmaxf(av1.y + x1.y + y1.y, 0.f);
                    av1.z = fmaxf(av1.z + x1.z + y1.z, 0.f);
                    av1.w = fmaxf(av1.w + x1.w + y1.w, 0.f);
                }
                if (RELUIN) {
                    av0.x = fmaxf(av0.x, 0.f); av0.y = fmaxf(av0.y, 0.f);
                    av0.z = fmaxf(av0.z, 0.f); av0.w = fmaxf(av0.w, 0.f);
                    av1.x = fmaxf(av1.x, 0.f); av1.y = fmaxf(av1.y, 0.f);
                    av1.z = fmaxf(av1.z, 0.f); av1.w = fmaxf(av1.w, 0.f);
                }
#pragma unroll
                for (int s = 0; s < 4; s++) {
                    float a0 = (s == 0) ? av0.x : (s == 1) ? av0.y : (s == 2) ? av0.z : av0.w;
                    float a1 = (s == 0) ? av1.x : (s == 1) ? av1.y : (s == 2) ? av1.z : av1.w;
                    const float4* w4 = reinterpret_cast<const float4*>(&sW[(kk * 4 + s) * HP]);
#pragma unroll
                    for (int j = 0; j < HP / 4; j++) {
                        float4 w = w4[j];
                        acc0[4 * j + 0] = fmaf(a0, w.x, acc0[4 * j + 0]);
                        acc0[4 * j + 1] = fmaf(a0, w.y, acc0[4 * j + 1]);
                        acc0[4 * j + 2] = fmaf(a0, w.z, acc0[4 * j + 2]);
                        acc0[4 * j + 3] = fmaf(a0, w.w, acc0[4 * j + 3]);
                        acc1[4 * j + 0] = fmaf(a1, w.x, acc1[4 * j + 0]);
                        acc1[4 * j + 1] = fmaf(a1, w.y, acc1[4 * j + 1]);
                        acc1[4 * j + 2] = fmaf(a1, w.z, acc1[4 * j + 2]);
                        acc1[4 * j + 3] = fmaf(a1, w.w, acc1[4 * j + 3]);
                    }
                }
            }

            float4* o40 = reinterpret_cast<float4*>(out + (size_t)r0 * HP);
#pragma unroll
            for (int j = 0; j < HP / 4; j++) {
                float4 v;
                v.x = acc0[4 * j + 0]; v.y = acc0[4 * j + 1];
                v.z = acc0[4 * j + 2]; v.w = acc0[4 * j + 3];
                if (MODE == 1) {
                    v.x = fmaxf(v.x, 0.f); v.y = fmaxf(v.y, 0.f);
                    v.z = fmaxf(v.z, 0.f); v.w = fmaxf(v.w, 0.f);
                }
                if (MODE == 2) {
                    float4 ov = o40[j];
                    v.x = ov.x + 0.5f * v.x; v.y = ov.y + 0.5f * v.y;
                    v.z = ov.z + 0.5f * v.z; v.w = ov.w + 0.5f * v.w;
                }
                o40[j] = v;
            }
            if (v1) {
                float4* o41 = reinterpret_cast<float4*>(out + (size_t)r1 * HP);
#pragma unroll
                for (int j = 0; j < HP / 4; j++) {
                    float4 v;
                    v.x = acc1[4 * j + 0]; v.y = acc1[4 * j + 1];
                    v.z = acc1[4 * j + 2]; v.w = acc1[4 * j + 3];
                    if (MODE == 1) {
                        v.x = fmaxf(v.x, 0.f); v.y = fmaxf(v.y, 0.f);
                        v.z = fmaxf(v.z, 0.f); v.w = fmaxf(v.w, 0.f);
                    }
                    if (MODE == 2) {
                        float4 ov = o41[j];
                        v.x = ov.x + 0.5f * v.x; v.y = ov.y + 0.5f * v.y;
                        v.z = ov.z + 0.5f * v.z; v.w = ov.w + 0.5f * v.w;
                    }
                    o41[j] = v;
                }
            }
        }
    }
}

// ================= persistent dual-output GEMM: outA = f(A)@WA, outB = f(A)@WB =======
// Zero bias. 1 row/thread, 128-row chunks. RELUIN applies relu to A rows.
template <int K, int HOUT, bool RELUIN>
__global__ void __launch_bounds__(128)
rowgemm_dual(const float* __restrict__ A,
             const float* __restrict__ WA, const float* __restrict__ WB,
             float* __restrict__ outA, float* __restrict__ outB, int M, int slot)
{
    constexpr int KP = (K + 3) & ~3;
    constexpr int HP = (HOUT + 3) & ~3;
    __shared__ float sWA[KP * HP];
    __shared__ float sWB[KP * HP];
    __shared__ int s_base;
    for (int i = threadIdx.x; i < KP * HP; i += 128) {
        int k = i / HP, j = i % HP;
        bool ok = (k < K && j < HOUT);
        sWA[i] = ok ? WA[k * HOUT + j] : 0.0f;
        sWB[i] = ok ? WB[k * HOUT + j] : 0.0f;
    }

    for (;;) {
        __syncthreads();
        if (threadIdx.x == 0) s_base = atomicAdd(&g_work[slot], 1);
        __syncthreads();
        int base = s_base * 128;
        if (base >= M) return;
        int r = base + threadIdx.x;
        if (r < M) {
            float accA[HP], accB[HP];
#pragma unroll
            for (int j = 0; j < HP; j++) { accA[j] = 0.0f; accB[j] = 0.0f; }

            const float4* a4 = reinterpret_cast<const float4*>(A + (size_t)r * KP);
#pragma unroll 1
            for (int kk = 0; kk < KP / 4; kk++) {
                float4 av = __ldg(&a4[kk]);
                if (RELUIN) {
                    av.x = fmaxf(av.x, 0.f); av.y = fmaxf(av.y, 0.f);
                    av.z = fmaxf(av.z, 0.f); av.w = fmaxf(av.w, 0.f);
                }
#pragma unroll
                for (int s = 0; s < 4; s++) {
                    float a = (s == 0) ? av.x : (s == 1) ? av.y : (s == 2) ? av.z : av.w;
                    const float4* wa4 = reinterpret_cast<const float4*>(&sWA[(kk * 4 + s) * HP]);
                    const float4* wb4 = reinterpret_cast<const float4*>(&sWB[(kk * 4 + s) * HP]);
#pragma unroll
                    for (int j = 0; j < HP / 4; j++) {
                        float4 wa = wa4[j];
                        float4 wb = wb4[j];
                        accA[4 * j + 0] = fmaf(a, wa.x, accA[4 * j + 0]);
                        accA[4 * j + 1] = fmaf(a, wa.y, accA[4 * j + 1]);
                        accA[4 * j + 2] = fmaf(a, wa.z, accA[4 * j + 2]);
                        accA[4 * j + 3] = fmaf(a, wa.w, accA[4 * j + 3]);
                        accB[4 * j + 0] = fmaf(a, wb.x, accB[4 * j + 0]);
                        accB[4 * j + 1] = fmaf(a, wb.y, accB[4 * j + 1]);
                        accB[4 * j + 2] = fmaf(a, wb.z, accB[4 * j + 2]);
                        accB[4 * j + 3] = fmaf(a, wb.w, accB[4 * j + 3]);
                    }
                }
            }

            float4* oA = reinterpret_cast<float4*>(outA + (size_t)r * HP);
            float4* oB = reinterpret_cast<float4*>(outB + (size_t)r * HP);
#pragma unroll
            for (int j = 0; j < HP / 4; j++) {
                float4 va, vb;
                va.x = accA[4 * j + 0]; va.y = accA[4 * j + 1];
                va.z = accA[4 * j + 2]; va.w = accA[4 * j + 3];
                vb.x = accB[4 * j + 0]; vb.y = accB[4 * j + 1];
                vb.z = accB[4 * j + 2]; vb.w = accB[4 * j + 3];
                oA[j] = va;
                oB[j] = vb;
            }
        }
    }
}

// ================= aggregation =================
__global__ void aggregate_kernel(const float* __restrict__ h, const float* __restrict__ ea,
                                 float* __restrict__ aggr)
{
    int warp = (blockIdx.x * blockDim.x + threadIdx.x) >> 5;
    int lane = threadIdx.x & 31;
    if (warp >= NN) return;
    int beg = g_rowstart[warp];
    int end = g_rowstart[warp + 1];
    bool has2 = lane < 2;
    int c2 = lane + 64;
    float a0 = 0.f, a1 = 0.f, a2 = 0.f;
    for (int p = beg; p < end; p++) {
        int s = g_srcs[p];
        const float* er = ea + (size_t)p * HS;
        const float* hr = h + (size_t)s * HS;
        a0 += fmaxf(hr[lane]      + er[lane],      0.f);
        a1 += fmaxf(hr[lane + 32] + er[lane + 32], 0.f);
        if (has2) a2 += fmaxf(hr[c2] + er[c2], 0.f);
    }
    const float* hd = h + (size_t)warp * HS;
    float* o = aggr + (size_t)warp * HS;
    o[lane]      = hd[lane]      + a0;
    o[lane + 32] = hd[lane + 32] + a1;
    if (has2) o[c2] = hd[c2] + a2;
}

// ================= BN =================
__global__ void bnstats_kernel(const float* __restrict__ z, int M)
{
    __shared__ float ssum[8][HH + 2];
    __shared__ float ssq [8][HH + 2];
    int c  = threadIdx.x;
    int ty = threadIdx.y;
    float s = 0.f, q = 0.f;
    for (int r = blockIdx.x * 8 + ty; r < M; r += gridDim.x * 8) {
        float v = z[(size_t)r * HS + c];
        s += v; q += v * v;
    }
    ssum[ty][c] = s; ssq[ty][c] = q;
    __syncthreads();
    for (int off = 4; off >= 1; off >>= 1) {
        if (ty < off) { ssum[ty][c] += ssum[ty + off][c]; ssq[ty][c] += ssq[ty + off][c]; }
        __syncthreads();
    }
    if (ty == 0) {
        atomicAdd(&g_sum[c],   ssum[0][c]);
        atomicAdd(&g_sumsq[c], ssq[0][c]);
    }
}

__global__ void bnfinal_kernel(int n)
{
    int c = threadIdx.x;
    if (c < HH) {
        float m = g_sum[c] / (float)n;
        float v = g_sumsq[c] / (float)n - m * m;
        g_mean[c] = m;
        g_invstd[c] = rsqrtf(v + BN_EPS);
        g_sum[c] = 0.0f;
        g_sumsq[c] = 0.0f;
    }
}

__global__ void hup_kernel(const float* __restrict__ gamma, const float* __restrict__ beta, int M)
{
    int c = threadIdx.x;
    int r = blockIdx.x * blockDim.y + threadIdx.y;
    if (r >= M) return;
    size_t i = (size_t)r * HS + c;
    float bn = (g_z[i] - g_mean[c]) * g_invstd[c] * gamma[c] + beta[c];
    g_h[i] = 0.5f * (g_h[i] + fmaxf(bn, 0.0f));
}

// ================= persistent final MLP layers 2+3 (COMB input) =================
__global__ void __launch_bounds__(128)
f23_kernel(const float* __restrict__ Rt, const float* __restrict__ Ra,
           const float* __restrict__ Rb,
           const int* __restrict__ ts, const int* __restrict__ td,
           const float* __restrict__ W2, const float* __restrict__ b2,
           const float* __restrict__ W3, const float* __restrict__ b3,
           float* __restrict__ out, int M, int slot)
{
    __shared__ float sW2[52 * 28];
    __shared__ float sW3[25 * 4];
    __shared__ float sb2[28];
    __shared__ float sb3[2];
    __shared__ int s_base;
    for (int i = threadIdx.x; i < 52 * 28; i += 128) {
        int k = i / 28, j = i % 28;
        sW2[i] = (k < 50 && j < 25) ? W2[k * 25 + j] : 0.0f;
    }
    for (int i = threadIdx.x; i < 25 * 4; i += 128) {
        int k = i / 4, j = i % 4;
        sW3[i] = (j < 2) ? W3[k * 2 + j] : 0.0f;
    }
    if (threadIdx.x < 28) sb2[threadIdx.x] = (threadIdx.x < 25) ? b2[threadIdx.x] : 0.0f;
    if (threadIdx.x < 2)  sb3[threadIdx.x] = b3[threadIdx.x];

    for (;;) {
        __syncthreads();
        if (threadIdx.x == 0) s_base = atomicAdd(&g_work[slot], 1);
        __syncthreads();
        int base = s_base * 256;
        if (base >= M) return;
        int r0 = base + threadIdx.x;
        if (r0 < M) {
            int r1 = r0 + 128;
            bool v1 = (r1 < M);
            int rb = v1 ? r1 : r0;

            float acc0[28], acc1[28];
#pragma unroll
            for (int j = 0; j < 28; j++) { acc0[j] = sb2[j]; acc1[j] = sb2[j]; }

            const float4* t40 = reinterpret_cast<const float4*>(Rt + (size_t)r0 * 52);
            const float4* t41 = reinterpret_cast<const float4*>(Rt + (size_t)rb * 52);
            const float4* pa0 = reinterpret_cast<const float4*>(Ra + (size_t)ts[r0] * 52);
            const float4* pb0 = reinterpret_cast<const float4*>(Rb + (size_t)td[r0] * 52);
            const float4* pa1 = reinterpret_cast<const float4*>(Ra + (size_t)ts[rb] * 52);
            const float4* pb1 = reinterpret_cast<const float4*>(Rb + (size_t)td[rb] * 52);
#pragma unroll 1
            for (int kk = 0; kk < 13; kk++) {
                float4 av0 = __ldg(&t40[kk]);
                float4 av1 = __ldg(&t41[kk]);
                float4 x0 = __ldg(&pa0[kk]), y0 = __ldg(&pb0[kk]);
                float4 x1 = __ldg(&pa1[kk]), y1 = __ldg(&pb1[kk]);
                av0.x = fmaxf(av0.x + x0.x + y0.x, 0.f);
                av0.y = fmaxf(av0.y + x0.y + y0.y, 0.f);
                av0.z = fmaxf(av0.z + x0.z + y0.z, 0.f);
                av0.w = fmaxf(av0.w + x0.w + y0.w, 0.f);
                av1.x = fmaxf(av1.x + x1.x + y1.x, 0.f);
                av1.y = fmaxf(av1.y + x1.y + y1.y, 0.f);
                av1.z = fmaxf(av1.z + x1.z + y1.z, 0.f);
                av1.w = fmaxf(av1.w + x1.w + y1.w, 0.f);
#pragma unroll
                for (int s = 0; s < 4; s++) {
                    float a0 = (s == 0) ? av0.x : (s == 1) ? av0.y : (s == 2) ? av0.z : av0.w;
                    float a1 = (s == 0) ? av1.x : (s == 1) ? av1.y : (s == 2) ? av1.z : av1.w;
                    const float4* w4 = reinterpret_cast<const float4*>(&sW2[(kk * 4 + s) * 28]);
#pragma unroll
                    for (int j = 0; j < 7; j++) {
                        float4 w = w4[j];
                        acc0[4 * j + 0] = fmaf(a0, w.x, acc0[4 * j + 0]);
                        acc0[4 * j + 1] = fmaf(a0, w.y, acc0[4 * j + 1]);
                        acc0[4 * j + 2] = fmaf(a0, w.z, acc0[4 * j + 2]);
                        acc0[4 * j + 3] = fmaf(a0, w.w, acc0[4 * j + 3]);
                        acc1[4 * j + 0] = fmaf(a1, w.x, acc1[4 * j + 0]);
                        acc1[4 * j + 1] = fmaf(a1, w.y, acc1[4 * j + 1]);
                        acc1[4 * j + 2] = fmaf(a1, w.z, acc1[4 * j + 2]);
                        acc1[4 * j + 3] = fmaf(a1, w.w, acc1[4 * j + 3]);
                    }
                }
            }

            float o00 = sb3[0], o01 = sb3[1], o10 = sb3[0], o11 = sb3[1];
#pragma unroll
            for (int k = 0; k < 25; k++) {
                float w0 = sW3[k * 4 + 0], w1 = sW3[k * 4 + 1];
                float a0 = fmaxf(acc0[k], 0.f);
                float a1 = fmaxf(acc1[k], 0.f);
                o00 = fmaf(a0, w0, o00); o01 = fmaf(a0, w1, o01);
                o10 = fmaf(a1, w0, o10); o11 = fmaf(a1, w1, o11);
            }
            out[(size_t)r0 * 2 + 0] = o00;
            out[(size_t)r0 * 2 + 1] = o01;
            if (v1) {
                out[(size_t)r1 * 2 + 0] = o10;
                out[(size_t)r1 * 2 + 1] = o11;
            }
        }
    }
}

// =======================================================================================
extern "C" void kernel_launch(void* const* d_in, const int* in_sizes, int n_in,
                              void* d_out, int out_size)
{
    const float *x, *edge_attr, *tea_in, *node_w, *node_b, *edge_w, *edge_b;
    const float *conv_w1, *conv_b1, *conv_w2, *conv_b2, *bn_gamma, *bn_beta;
    const float *emlp_w1, *emlp_b1, *emlp_w2, *emlp_b2;
    const float *mlp_w1, *mlp_b1, *mlp_w2, *mlp_b2, *mlp_w3, *mlp_b3;
    const int *edge_index, *eli;

    if (in_sizes[1] == 2 * EE) {
        x          = (const float*)d_in[0];
        edge_index = (const int*)  d_in[1];
        edge_attr  = (const float*)d_in[2];
        eli        = (const int*)  d_in[3];
        tea_in     = (const float*)d_in[4];
        node_w = (const float*)d_in[5];  node_b = (const float*)d_in[6];
        edge_w = (const float*)d_in[7];  edge_b = (const float*)d_in[8];
        conv_w1 = (const float*)d_in[9];  conv_b1 = (const float*)d_in[10];
        conv_w2 = (const float*)d_in[11]; conv_b2 = (const float*)d_in[12];
        bn_gamma = (const float*)d_in[13]; bn_beta = (const float*)d_in[14];
        emlp_w1 = (const float*)d_in[15]; emlp_b1 = (const float*)d_in[16];
        emlp_w2 = (const float*)d_in[17]; emlp_b2 = (const float*)d_in[18];
        mlp_w1 = (const float*)d_in[19]; mlp_b1 = (const float*)d_in[20];
        mlp_w2 = (const float*)d_in[21]; mlp_b2 = (const float*)d_in[22];
        mlp_w3 = (const float*)d_in[23]; mlp_b3 = (const float*)d_in[24];
    } else {
        x         = (const float*)d_in[0];
        edge_attr = (const float*)d_in[1];
        tea_in    = (const float*)d_in[2];
        node_w = (const float*)d_in[3];  node_b = (const float*)d_in[4];
        edge_w = (const float*)d_in[5];  edge_b = (const float*)d_in[6];
        conv_w1 = (const float*)d_in[7];  conv_b1 = (const float*)d_in[8];
        conv_w2 = (const float*)d_in[9];  conv_b2 = (const float*)d_in[10];
        bn_gamma = (const float*)d_in[11]; bn_beta = (const float*)d_in[12];
        emlp_w1 = (const float*)d_in[13]; emlp_b1 = (const float*)d_in[14];
        emlp_w2 = (const float*)d_in[15]; emlp_b2 = (const float*)d_in[16];
        mlp_w1 = (const float*)d_in[17]; mlp_b1 = (const float*)d_in[18];
        mlp_w2 = (const float*)d_in[19]; mlp_b2 = (const float*)d_in[20];
        mlp_w3 = (const float*)d_in[21]; mlp_b3 = (const float*)d_in[22];
        edge_index = (const int*)d_in[23];
        eli        = (const int*)d_in[24];
    }

    const int* e_src = edge_index;
    const int* e_dst = edge_index + EE;
    const int* tsrc  = eli;
    const int* tdst  = eli + ETT;

    float *p_h, *p_ea, *p_tea, *p_aggr, *p_t, *p_z, *p_ehid, *p_o1, *p_zb;
    int *p_perm;
    cudaGetSymbolAddress((void**)&p_h,    g_h);
    cudaGetSymbolAddress((void**)&p_ea,   g_ea);
    cudaGetSymbolAddress((void**)&p_tea,  g_tea);
    cudaGetSymbolAddress((void**)&p_aggr, g_aggr);
    cudaGetSymbolAddress((void**)&p_t,    g_t);
    cudaGetSymbolAddress((void**)&p_z,    g_z);
    cudaGetSymbolAddress((void**)&p_ehid, g_ehid);
    cudaGetSymbolAddress((void**)&p_o1,   g_o1);
    cudaGetSymbolAddress((void**)&p_zb,   g_zerob);
    cudaGetSymbolAddress((void**)&p_perm, g_perm);

    // ---- CSR build (also zeroes g_work) ----
    zero_cnt_kernel<<<cdiv(NN, 256), 256>>>();
    hist_kernel<<<cdiv(EE, 256), 256>>>(e_dst);
    scan1_kernel<<<cdiv(NN, 1024), 1024>>>();
    scan2_kernel<<<1, 128>>>(cdiv(NN, 1024));
    scan3_kernel<<<cdiv(NN, 256), 256>>>();
    place_kernel<<<cdiv(EE, 256), 256>>>(e_src, e_dst);

    // ---- embeddings (persistent, slots 0-2) ----
    rowgemm2<FFI, HH, 0, false, false, false><<<gmin(cdiv(NN, 256), GMAX), 128>>>(
        x, node_w, node_b, p_h, nullptr, NN, 0, nullptr, nullptr, nullptr, nullptr);
    rowgemm2<DDI, HH, 0, true, false, false><<<gmin(cdiv(EE, 256), GMAX), 128>>>(
        edge_attr, edge_w, edge_b, p_ea, p_perm, EE, 1, nullptr, nullptr, nullptr, nullptr);
    rowgemm2<DDI, HH, 0, false, false, false><<<gmin(cdiv(ETT, 256), GMAX), 128>>>(
        tea_in, edge_w, edge_b, p_tea, nullptr, ETT, 2, nullptr, nullptr, nullptr, nullptr);

    // ---- layers (slots s0..s0+4) ----
    for (int l = 0; l < LLY; l++) {
        int s0 = 3 + l * 5;
        const float* W1 = emlp_w1 + l * 3 * HH * HH;   // rows 0-65=a, 66-131=b, 132-197=c
        aggregate_kernel<<<cdiv(NN, 8), 256>>>(p_h, p_ea, p_aggr);
        rowgemm2<HH, HH, 1, false, false, false><<<gmin(cdiv(NN, 256), GMAX), 128>>>(
            p_aggr, conv_w1 + l * HH * HH, conv_b1 + l * HH, p_t, nullptr, NN, s0,
            nullptr, nullptr, nullptr, nullptr);
        rowgemm2<HH, HH, 0, false, false, false><<<gmin(cdiv(NN, 256), GMAX), 128>>>(
            p_t, conv_w2 + l * HH * HH, conv_b2 + l * HH, p_z, nullptr, NN, s0 + 1,
            nullptr, nullptr, nullptr, nullptr);
        {
            dim3 bs(HH, 8);
            bnstats_kernel<<<264, bs>>>(p_z, NN);
        }
        bnfinal_kernel<<<1, HH>>>(NN);
        {
            dim3 bs(HH, 4);
            hup_kernel<<<cdiv(NN, 4), bs>>>(bn_gamma + l * HH, bn_beta + l * HH, NN);
        }
        // edge update, factored + fused combine:
        // Pa = h@W1a, Pb = h@W1b in ONE dual-output kernel; Ptea = tea@W1c + b1 (edges)
        rowgemm_dual<HH, HH, false><<<gmin(cdiv(NN, 128), GMAX), 128>>>(
            p_h, W1, W1 + HH * HH, p_t, p_aggr, NN, s0 + 2);
        rowgemm2<HH, HH, 0, false, false, false><<<gmin(cdiv(ETT, 256), GMAX), 128>>>(
            p_tea, W1 + 2 * HH * HH, emlp_b1 + l * HH, p_ehid, nullptr, ETT, s0 + 3,
            nullptr, nullptr, nullptr, nullptr);
        // tea += 0.5*(relu(Pa[ts]+Pb[td]+Ptea) @ W2 + b2)
        rowgemm2<HH, HH, 2, false, false, true><<<gmin(cdiv(ETT, 256), GMAX), 128>>>(
            p_ehid, emlp_w2 + l * HH * HH, emlp_b2 + l * HH, p_tea, nullptr, ETT, s0 + 4,
            p_t, p_aggr, tsrc, tdst);
    }

    // ---- final classifier, factored + fused combine (slots 13-15) ----
    rowgemm_dual<HH, 50, true><<<gmin(cdiv(NN, 128), GMAX), 128>>>(
        p_h, mlp_w1, mlp_w1 + HH * 50, p_t, p_aggr, NN, 13);
    rowgemm2<HH, 50, 0, false, false, false><<<gmin(cdiv(ETT, 256), GMAX), 128>>>(
        p_tea, mlp_w1 + 2 * HH * 50, mlp_b1, p_o1, nullptr, ETT, 14,
        nullptr, nullptr, nullptr, nullptr);
    f23_kernel<<<gmin(cdiv(ETT, 256), GMAX), 128>>>(p_o1, p_t, p_aggr, tsrc, tdst,
                                                    mlp_w2, mlp_b2, mlp_w3, mlp_b3,
                                                    (float*)d_out, ETT, 15);
}